// round 1
// baseline (speedup 1.0000x reference)
#include <cuda_runtime.h>
#include <math.h>

#define BB 32
#define NN 1024
#define HH 256

// Scratch (allocation-free rule: __device__ globals)
static __device__ float g_Wh[BB * NN * HH];   // 32 MB
static __device__ float g_s1[BB * NN];
static __device__ float g_s2[BB * NN];

// ---------------------------------------------------------------------------
// Kernel 1: Wh[b,n,:] = inp[b,n,:] @ (sel ? W_i : W_c)
// sel = (n >= l[b,0] && n < l[b,1]) — contiguous range, so 64-row tiles are
// almost always uniform; mixed tiles (<=2 per batch per col tile) run 2 passes.
// ---------------------------------------------------------------------------
#define BM 64
#define BN 64
#define BK 16

__global__ __launch_bounds__(256) void wh_gemm_kernel(
    const float* __restrict__ inp, const int* __restrict__ l,
    const float* __restrict__ Wi, const float* __restrict__ Wc,
    float* __restrict__ Wh)
{
    __shared__ float As[BM][BK];
    __shared__ float Ws[BK][BN];

    const int tid = threadIdx.x;
    const int tx = tid & 15;        // 16 col groups
    const int ty = tid >> 4;        // 16 row groups
    const int rowTile = blockIdx.x * BM;     // global row base (b*N + n0)
    const int colBase = blockIdx.y * BN;
    const int b  = rowTile >> 10;            // N=1024 per batch; tiles never span batches
    const int n0 = rowTile & 1023;
    const int l0 = l[2 * b];
    const int l1 = l[2 * b + 1];

    const bool mixed = (l0 > n0 && l0 < n0 + BM) || (l1 > n0 && l1 < n0 + BM);
    const bool sel0  = (n0 >= l0 && n0 < l1);
    const int npass  = mixed ? 2 : 1;

    for (int pass = 0; pass < npass; ++pass) {
        const float* W = mixed ? (pass == 0 ? Wi : Wc) : (sel0 ? Wi : Wc);

        float acc[4][4];
        #pragma unroll
        for (int m = 0; m < 4; ++m)
            #pragma unroll
            for (int n = 0; n < 4; ++n) acc[m][n] = 0.0f;

        for (int k0 = 0; k0 < HH; k0 += BK) {
            // Load inp tile 64x16 (one float4 per thread)
            {
                int r = tid >> 2, c = (tid & 3) * 4;
                *(float4*)&As[r][c] =
                    *(const float4*)&inp[(size_t)(rowTile + r) * HH + k0 + c];
            }
            // Load W tile 16x64 (one float4 per thread)
            {
                int r = tid >> 4, c = (tid & 15) * 4;
                *(float4*)&Ws[r][c] =
                    *(const float4*)&W[(size_t)(k0 + r) * HH + colBase + c];
            }
            __syncthreads();

            #pragma unroll
            for (int kk = 0; kk < BK; ++kk) {
                float a[4], bb[4];
                #pragma unroll
                for (int m = 0; m < 4; ++m) a[m] = As[ty * 4 + m][kk];
                #pragma unroll
                for (int n = 0; n < 4; ++n) bb[n] = Ws[kk][tx * 4 + n];
                #pragma unroll
                for (int m = 0; m < 4; ++m)
                    #pragma unroll
                    for (int n = 0; n < 4; ++n)
                        acc[m][n] = fmaf(a[m], bb[n], acc[m][n]);
            }
            __syncthreads();
        }

        #pragma unroll
        for (int m = 0; m < 4; ++m) {
            int nrow = n0 + ty * 4 + m;
            bool sel = (nrow >= l0 && nrow < l1);
            bool doWrite = !mixed || (sel == (pass == 0));
            if (doWrite) {
                float4 v = make_float4(acc[m][0], acc[m][1], acc[m][2], acc[m][3]);
                *(float4*)&Wh[(size_t)(rowTile + ty * 4 + m) * HH + colBase + tx * 4] = v;
            }
        }
    }
}

// ---------------------------------------------------------------------------
// Kernel 2: s1[r] = Wh[r,:] . a[0:H],  s2[r] = Wh[r,:] . a[H:2H]
// ---------------------------------------------------------------------------
__global__ __launch_bounds__(256) void dots_kernel(
    const float* __restrict__ Wh, const float* __restrict__ a,
    float* __restrict__ s1, float* __restrict__ s2)
{
    const int row = blockIdx.x;
    const int tid = threadIdx.x;
    float v  = Wh[(size_t)row * HH + tid];
    float p1 = v * a[tid];
    float p2 = v * a[HH + tid];

    __shared__ float r1[256], r2[256];
    r1[tid] = p1; r2[tid] = p2;
    __syncthreads();
    for (int s = 128; s > 0; s >>= 1) {
        if (tid < s) { r1[tid] += r1[tid + s]; r2[tid] += r2[tid + s]; }
        __syncthreads();
    }
    if (tid == 0) { s1[row] = r1[0]; s2[row] = r2[0]; }
}

// ---------------------------------------------------------------------------
// Kernel 3: sparse attention + aggregation + elu.
// One CTA (256 thr) per (b,i) row. Scan A row, compact nnz (A+I), exact
// softmax over ~52 entries, gather-accumulate Wh rows, elu.
// ---------------------------------------------------------------------------
__global__ __launch_bounds__(256) void attn_kernel(
    const float* __restrict__ A, const float* __restrict__ Wh,
    const float* __restrict__ s1, const float* __restrict__ s2,
    float* __restrict__ out)
{
    const int bi = blockIdx.x;        // b*N + i
    const int b  = bi >> 10;
    const int i  = bi & 1023;
    const int tid = threadIdx.x;

    __shared__ int   cnt;
    __shared__ int   idxs[NN];
    __shared__ float xs[NN];
    __shared__ float red[256];

    if (tid == 0) cnt = 0;
    __syncthreads();

    const float* Arow = A + (size_t)bi * NN;
    const float* s2b  = s2 + (size_t)b * NN;
    const float  s1i  = s1[bi];

    // Phase A: scan + compact + per-thread max. 4 contiguous floats/thread.
    float lmax = -INFINITY;
    {
        float4 av4 = *(const float4*)&Arow[tid * 4];
        float av[4] = {av4.x, av4.y, av4.z, av4.w};
        #pragma unroll
        for (int q = 0; q < 4; ++q) {
            int j = tid * 4 + q;
            float aval = av[q] + ((j == i) ? 1.0f : 0.0f);
            if (aval > 0.0f) {
                float x = (s1i + s2b[j]) * aval;
                x = (x > 0.0f) ? x : 0.2f * x;      // leaky relu
                int p = atomicAdd(&cnt, 1);
                idxs[p] = j;
                xs[p]   = x;
                lmax = fmaxf(lmax, x);
            }
        }
    }
    red[tid] = lmax;
    __syncthreads();
    for (int s = 128; s > 0; s >>= 1) {
        if (tid < s) red[tid] = fmaxf(red[tid], red[tid + s]);
        __syncthreads();
    }
    const float m = red[0];
    const int   c = cnt;
    __syncthreads();

    // Phase B: weights + sum
    float lz = 0.0f;
    for (int p = tid; p < c; p += 256) {
        float w = expf(xs[p] - m);
        xs[p] = w;
        lz += w;
    }
    red[tid] = lz;
    __syncthreads();
    for (int s = 128; s > 0; s >>= 1) {
        if (tid < s) red[tid] += red[tid + s];
        __syncthreads();
    }
    const float Zinv = 1.0f / red[0];
    __syncthreads();

    // Phase C: gather-accumulate (thread tid owns feature dim h=tid)
    const float* Whb = Wh + (size_t)b * NN * HH;
    float acc = 0.0f;
    int p = 0;
    for (; p + 4 <= c; p += 4) {
        int j0 = idxs[p], j1 = idxs[p + 1], j2 = idxs[p + 2], j3 = idxs[p + 3];
        float w0 = xs[p], w1 = xs[p + 1], w2 = xs[p + 2], w3 = xs[p + 3];
        float v0 = Whb[(size_t)j0 * HH + tid];
        float v1 = Whb[(size_t)j1 * HH + tid];
        float v2 = Whb[(size_t)j2 * HH + tid];
        float v3 = Whb[(size_t)j3 * HH + tid];
        acc = fmaf(w0, v0, acc);
        acc = fmaf(w1, v1, acc);
        acc = fmaf(w2, v2, acc);
        acc = fmaf(w3, v3, acc);
    }
    for (; p < c; ++p)
        acc = fmaf(xs[p], Whb[(size_t)idxs[p] * HH + tid], acc);

    acc *= Zinv;
    // elu (alpha=1)
    out[(size_t)bi * HH + tid] = (acc > 0.0f) ? acc : expm1f(acc);
}

// ---------------------------------------------------------------------------
extern "C" void kernel_launch(void* const* d_in, const int* in_sizes, int n_in,
                              void* d_out, int out_size)
{
    const float* inp = (const float*)d_in[0];   // [B,N,H]
    const float* A   = (const float*)d_in[1];   // [B,N,N]
    const int*   l   = (const int*)  d_in[2];   // [B,2]
    const float* Wi  = (const float*)d_in[3];   // [H,H]
    const float* Wc  = (const float*)d_in[4];   // [H,H]
    const float* a   = (const float*)d_in[5];   // [2H,1]
    float* out = (float*)d_out;

    float *Wh, *s1, *s2;
    cudaGetSymbolAddress((void**)&Wh, g_Wh);
    cudaGetSymbolAddress((void**)&s1, g_s1);
    cudaGetSymbolAddress((void**)&s2, g_s2);

    dim3 g1(BB * NN / BM, HH / BN);
    wh_gemm_kernel<<<g1, 256>>>(inp, l, Wi, Wc, Wh);

    dots_kernel<<<BB * NN, 256>>>(Wh, a, s1, s2);

    attn_kernel<<<BB * NN, 256>>>(A, Wh, s1, s2, out);
}

// round 8
// speedup vs baseline: 1.9439x; 1.9439x over previous
#include <cuda_runtime.h>
#include <cuda_fp16.h>
#include <cuda_bf16.h>
#include <math.h>
#include <stdint.h>

#define BB 32
#define NN 1024
#define HH 256

// Scratch (__device__ globals; no allocations allowed)
static __device__ __half        g_WhH[BB * NN * HH];   // 16 MB fp16 Wh (gather operand)
static __device__ float         g_s1[BB * NN];
static __device__ float         g_s2[BB * NN];
static __device__ __nv_bfloat16 g_WT[4][HH * HH];      // WiH, WiL, WcH, WcL, transposed [n][k]

// ---------------------------------------------------------------------------
__device__ __forceinline__ uint32_t smem_u32(const void* p) {
    uint32_t a;
    asm("{ .reg .u64 t; cvta.to.shared.u64 t, %1; cvt.u32.u64 %0, t; }" : "=r"(a) : "l"(p));
    return a;
}

#define LDSM_X4(r0, r1, r2, r3, addr) \
    asm volatile("ldmatrix.sync.aligned.m8n8.x4.shared.b16 {%0,%1,%2,%3}, [%4];" \
                 : "=r"(r0), "=r"(r1), "=r"(r2), "=r"(r3) : "r"(addr))

#define MMA(d, a, b0r, b1r) \
    asm volatile("mma.sync.aligned.m16n8k16.row.col.f32.bf16.bf16.f32 " \
                 "{%0,%1,%2,%3}, {%4,%5,%6,%7}, {%8,%9}, {%0,%1,%2,%3};" \
                 : "+f"((d)[0]), "+f"((d)[1]), "+f"((d)[2]), "+f"((d)[3]) \
                 : "r"((a)[0]), "r"((a)[1]), "r"((a)[2]), "r"((a)[3]), \
                   "r"(b0r), "r"(b1r))

// ---------------------------------------------------------------------------
// Kernel 0: split W_i/W_c into transposed bf16 hi/lo: WT[n][k] = W[k][n]
// ---------------------------------------------------------------------------
__global__ __launch_bounds__(256) void wsplit_kernel(
    const float* __restrict__ Wi, const float* __restrict__ Wc)
{
    int idx = blockIdx.x * 256 + threadIdx.x;          // 0 .. 2*65536-1
    int which = idx >> 16;
    int e = idx & 65535;
    int n = e >> 8, k = e & 255;
    const float* W = which ? Wc : Wi;
    float x = W[k * HH + n];
    __nv_bfloat16 h = __float2bfloat16(x);
    __nv_bfloat16 lo = __float2bfloat16(x - __bfloat162float(h));
    g_WT[which * 2][n * HH + k] = h;
    g_WT[which * 2 + 1][n * HH + k] = lo;
}

// ---------------------------------------------------------------------------
// Kernel 1: mma.sync bf16 3-term split GEMM, 128 rows x 256 cols per CTA,
// 512 threads (warp grid 4 rows x 4 cols, warp tile 32x64). K chunks of 32.
// Epilogue: fused s1/s2 dots + fp16 Wh store. Mixed l-boundary tiles: 2 passes.
// NOTE: W-selection masks compare the WITHIN-BATCH node index (n0 + local row)
// against l0/l1 — the root-cause fix for rounds 3/4/6/7.
// ---------------------------------------------------------------------------
#define PADK 40                          // padded k-stride (bf16 elems) per smem row
#define OFF_A   0                        // bf16[2][128][PADK]
#define OFF_B   (2 * 128 * PADK * 2)     // bf16[2][256][PADK]  (20480)
#define OFF_AV  (OFF_B + 2 * 256 * PADK * 2)   // float[512]     (61440)
#define OFF_RED (OFF_AV + 512 * 4)             // float[4][128][2] (63488)
#define SMEM_TOT (OFF_RED + 4 * 128 * 2 * 4)   // 67584

__global__ __launch_bounds__(512) void gemm_kernel(
    const float* __restrict__ inp, const int* __restrict__ l,
    const float* __restrict__ avec)
{
    extern __shared__ char smem[];
    const uint32_t sb  = smem_u32(smem);
    const uint32_t sbA = sb + OFF_A;
    const uint32_t sbB = sb + OFF_B;
    float* sAv  = (float*)(smem + OFF_AV);
    float* sRed = (float*)(smem + OFF_RED);

    const int tid = threadIdx.x, lane = tid & 31, wid = tid >> 5;
    const int warpRow = wid >> 2, warpCol = wid & 3;
    const int rowTile = blockIdx.x * 128;
    const int b = rowTile >> 10;
    const int n0 = rowTile & 1023;
    const int l0 = l[2 * b], l1 = l[2 * b + 1];
    const bool mixed = (l0 > n0 && l0 < n0 + 128) || (l1 > n0 && l1 < n0 + 128);
    const bool sel0  = (n0 >= l0 && n0 < l1);
    const int npass  = mixed ? 2 : 1;

    sAv[tid] = avec[tid];   // 512 threads load exactly a[0..511]

    for (int pass = 0; pass < npass; ++pass) {
        const bool useWi = mixed ? (pass == 0) : sel0;
        const __nv_bfloat16* __restrict__ Bh = g_WT[useWi ? 0 : 2];
        const __nv_bfloat16* __restrict__ Bl = g_WT[useWi ? 1 : 3];

        float acc[2][8][4];
        #pragma unroll
        for (int mt = 0; mt < 2; ++mt)
            #pragma unroll
            for (int nt = 0; nt < 8; ++nt)
                #pragma unroll
                for (int e = 0; e < 4; ++e) acc[mt][nt][e] = 0.0f;

        for (int kc = 0; kc < 8; ++kc) {
            const int k0 = kc * 32;
            __syncthreads();   // previous chunk's compute done

            // ---- A: 128x32 fp32 -> bf16 hi/lo ----
            #pragma unroll
            for (int it = 0; it < 2; ++it) {
                int f = tid + it * 512;            // 0..1023
                int r = f >> 3, c4 = (f & 7) * 4;
                float4 v = *(const float4*)(inp + (size_t)(rowTile + r) * HH + k0 + c4);
                float xv[4] = {v.x, v.y, v.z, v.w};
                unsigned short h[4], q[4];
                #pragma unroll
                for (int e = 0; e < 4; ++e) {
                    __nv_bfloat16 bh = __float2bfloat16(xv[e]);
                    h[e] = __bfloat16_as_ushort(bh);
                    q[e] = __bfloat16_as_ushort(
                        __float2bfloat16(xv[e] - __bfloat162float(bh)));
                }
                uint2 hv = make_uint2(h[0] | ((uint32_t)h[1] << 16),
                                      h[2] | ((uint32_t)h[3] << 16));
                uint2 lv = make_uint2(q[0] | ((uint32_t)q[1] << 16),
                                      q[2] | ((uint32_t)q[3] << 16));
                *(uint2*)(smem + OFF_A + ((size_t)r * PADK + c4) * 2) = hv;
                *(uint2*)(smem + OFF_A + ((size_t)(128 + r) * PADK + c4) * 2) = lv;
            }
            // ---- B: 256x32 bf16 hi/lo (pre-split) ----
            #pragma unroll
            for (int it = 0; it < 2; ++it) {
                int gI = tid + it * 512;           // 0..1023
                int r = gI >> 2, c8 = (gI & 3) * 8;
                int4 vh = *(const int4*)(Bh + (size_t)r * HH + k0 + c8);
                int4 vl = *(const int4*)(Bl + (size_t)r * HH + k0 + c8);
                *(int4*)(smem + OFF_B + ((size_t)r * PADK + c8) * 2) = vh;
                *(int4*)(smem + OFF_B + ((size_t)(256 + r) * PADK + c8) * 2) = vl;
            }
            __syncthreads();

            // ---- compute ----
            #pragma unroll
            for (int ks = 0; ks < 2; ++ks) {
                const int kk = ks * 16;
                uint32_t ah[2][4], al[2][4];
                #pragma unroll
                for (int mt = 0; mt < 2; ++mt) {
                    int row = warpRow * 32 + mt * 16 + (lane & 15);
                    int kcol = kk + (lane >> 4) * 8;
                    uint32_t ad = sbA + (uint32_t)(row * PADK + kcol) * 2;
                    LDSM_X4(ah[mt][0], ah[mt][1], ah[mt][2], ah[mt][3], ad);
                    LDSM_X4(al[mt][0], al[mt][1], al[mt][2], al[mt][3],
                            ad + 128 * PADK * 2);
                }
                #pragma unroll
                for (int p = 0; p < 4; ++p) {
                    int row = warpCol * 64 + p * 16 + (lane & 7) + ((lane >> 4) << 3);
                    int kcol = kk + (((lane >> 3) & 1) << 3);
                    uint32_t bd = sbB + (uint32_t)(row * PADK + kcol) * 2;
                    uint32_t bh[4], bl[4];
                    LDSM_X4(bh[0], bh[1], bh[2], bh[3], bd);
                    LDSM_X4(bl[0], bl[1], bl[2], bl[3], bd + 256 * PADK * 2);
                    #pragma unroll
                    for (int mt = 0; mt < 2; ++mt) {
                        MMA(acc[mt][2 * p],     ah[mt], bh[0], bh[1]);
                        MMA(acc[mt][2 * p],     al[mt], bh[0], bh[1]);
                        MMA(acc[mt][2 * p],     ah[mt], bl[0], bl[1]);
                        MMA(acc[mt][2 * p + 1], ah[mt], bh[2], bh[3]);
                        MMA(acc[mt][2 * p + 1], al[mt], bh[2], bh[3]);
                        MMA(acc[mt][2 * p + 1], ah[mt], bl[2], bl[3]);
                    }
                }
            }
        }

        // ---- epilogue: fp16 Wh store + fused s1/s2 dots ----
        __syncthreads();
        const int g = lane >> 2, qc = (lane & 3) * 2;
        #pragma unroll
        for (int mt = 0; mt < 2; ++mt) {
            int lr0 = warpRow * 32 + mt * 16 + g;
            int lr1 = lr0 + 8;
            int gr0 = rowTile + lr0, gr1 = rowTile + lr1;   // global (addressing)
            int nr0 = n0 + lr0, nr1 = n0 + lr1;             // within-batch (masking)
            bool dw0 = !mixed || (((nr0 >= l0) && (nr0 < l1)) == useWi);
            bool dw1 = !mixed || (((nr1 >= l0) && (nr1 < l1)) == useWi);
            float s1r0 = 0, s2r0 = 0, s1r1 = 0, s2r1 = 0;
            #pragma unroll
            for (int nt = 0; nt < 8; ++nt) {
                int col = warpCol * 64 + nt * 8 + qc;
                float a0 = sAv[col], a1 = sAv[col + 1];
                float b0 = sAv[256 + col], b1 = sAv[256 + col + 1];
                float c0 = acc[mt][nt][0], c1 = acc[mt][nt][1];
                float c2 = acc[mt][nt][2], c3 = acc[mt][nt][3];
                s1r0 = fmaf(c0, a0, fmaf(c1, a1, s1r0));
                s2r0 = fmaf(c0, b0, fmaf(c1, b1, s2r0));
                s1r1 = fmaf(c2, a0, fmaf(c3, a1, s1r1));
                s2r1 = fmaf(c2, b0, fmaf(c3, b1, s2r1));
                if (dw0)
                    *(__half2*)(g_WhH + (size_t)gr0 * HH + col) = __floats2half2_rn(c0, c1);
                if (dw1)
                    *(__half2*)(g_WhH + (size_t)gr1 * HH + col) = __floats2half2_rn(c2, c3);
            }
            #pragma unroll
            for (int d = 1; d <= 2; d <<= 1) {
                s1r0 += __shfl_xor_sync(0xffffffffu, s1r0, d);
                s2r0 += __shfl_xor_sync(0xffffffffu, s2r0, d);
                s1r1 += __shfl_xor_sync(0xffffffffu, s1r1, d);
                s2r1 += __shfl_xor_sync(0xffffffffu, s2r1, d);
            }
            if ((lane & 3) == 0) {
                sRed[(warpCol * 128 + lr0) * 2 + 0] = s1r0;
                sRed[(warpCol * 128 + lr0) * 2 + 1] = s2r0;
                sRed[(warpCol * 128 + lr1) * 2 + 0] = s1r1;
                sRed[(warpCol * 128 + lr1) * 2 + 1] = s2r1;
            }
        }
        __syncthreads();
        if (tid < 128) {
            int grow = rowTile + tid;      // global (addressing)
            int nrow = n0 + tid;           // within-batch (masking)
            bool dw = !mixed || (((nrow >= l0) && (nrow < l1)) == useWi);
            if (dw) {
                float v1 = 0, v2 = 0;
                #pragma unroll
                for (int wc = 0; wc < 4; ++wc) {
                    v1 += sRed[(wc * 128 + tid) * 2 + 0];
                    v2 += sRed[(wc * 128 + tid) * 2 + 1];
                }
                g_s1[grow] = v1;
                g_s2[grow] = v2;
            }
        }
        __syncthreads();
    }
}

// ---------------------------------------------------------------------------
// Kernel 2: sparse attention + aggregation + elu. 128 threads per (b,i) row.
// Ballot/scan compaction (no atomics), exact softmax, half2 gather, fp32 acc.
// ---------------------------------------------------------------------------
__global__ __launch_bounds__(128) void attn_kernel(
    const float* __restrict__ A, float* __restrict__ out)
{
    __shared__ int   s_idx[NN];
    __shared__ float s_x[NN];
    __shared__ int   s_wcnt[4];
    __shared__ float s_red[8];

    const int bi = blockIdx.x;
    const int b = bi >> 10, i = bi & 1023;
    const int tid = threadIdx.x, lane = tid & 31, w = tid >> 5;
    const float* Arow = A + (size_t)bi * NN;
    const float* s2b = g_s2 + (size_t)b * NN;
    const float s1i = g_s1[bi];

    // Phase A: scan 8 contiguous j's per thread
    float av[8];
    {
        float4 v0 = *(const float4*)(Arow + tid * 8);
        float4 v1 = *(const float4*)(Arow + tid * 8 + 4);
        av[0] = v0.x; av[1] = v0.y; av[2] = v0.z; av[3] = v0.w;
        av[4] = v1.x; av[5] = v1.y; av[6] = v1.z; av[7] = v1.w;
    }
    unsigned pbits = 0;
    int tcnt = 0;
    float xv[8];
    float lmax = -INFINITY;
    #pragma unroll
    for (int q = 0; q < 8; ++q) {
        int j = tid * 8 + q;
        float aval = av[q] + ((j == i) ? 1.0f : 0.0f);   // A + I (diag may be 2)
        if (aval > 0.0f) {
            float x = (s1i + s2b[j]) * aval;
            x = (x > 0.0f) ? x : 0.2f * x;               // leaky relu
            xv[q] = x;
            pbits |= (1u << q);
            ++tcnt;
            lmax = fmaxf(lmax, x);
        }
    }
    int pre = tcnt;
    #pragma unroll
    for (int d = 1; d < 32; d <<= 1) {
        int t = __shfl_up_sync(0xffffffffu, pre, d);
        if (lane >= d) pre += t;
    }
    if (lane == 31) s_wcnt[w] = pre;
    float wm = lmax;
    #pragma unroll
    for (int d = 16; d > 0; d >>= 1) wm = fmaxf(wm, __shfl_xor_sync(0xffffffffu, wm, d));
    if (lane == 0) s_red[w] = wm;
    __syncthreads();
    int base = pre - tcnt;
    for (int k = 0; k < w; ++k) base += s_wcnt[k];
    const int c = s_wcnt[0] + s_wcnt[1] + s_wcnt[2] + s_wcnt[3];
    const float m = fmaxf(fmaxf(s_red[0], s_red[1]), fmaxf(s_red[2], s_red[3]));
    #pragma unroll
    for (int q = 0; q < 8; ++q) {
        if (pbits & (1u << q)) { s_idx[base] = tid * 8 + q; s_x[base] = xv[q]; ++base; }
    }
    __syncthreads();

    // Phase B: exp + sum (exact softmax over compacted entries)
    float lz = 0.0f;
    for (int p = tid; p < c; p += 128) {
        float wg = expf(s_x[p] - m);
        s_x[p] = wg;
        lz += wg;
    }
    #pragma unroll
    for (int d = 16; d > 0; d >>= 1) lz += __shfl_xor_sync(0xffffffffu, lz, d);
    if (lane == 0) s_red[4 + w] = lz;
    __syncthreads();
    const float Zi = 1.0f / (s_red[4] + s_red[5] + s_red[6] + s_red[7]);

    // Phase C: half2 gather-accumulate; thread owns features (2*tid, 2*tid+1)
    const __half2* Wb = (const __half2*)g_WhH + (size_t)b * NN * 128;
    float accx = 0.0f, accy = 0.0f;
    int p = 0;
    for (; p + 4 <= c; p += 4) {
        int j0 = s_idx[p], j1 = s_idx[p + 1], j2 = s_idx[p + 2], j3 = s_idx[p + 3];
        float w0 = s_x[p], w1 = s_x[p + 1], w2 = s_x[p + 2], w3 = s_x[p + 3];
        float2 f0 = __half22float2(Wb[(size_t)j0 * 128 + tid]);
        float2 f1 = __half22float2(Wb[(size_t)j1 * 128 + tid]);
        float2 f2 = __half22float2(Wb[(size_t)j2 * 128 + tid]);
        float2 f3 = __half22float2(Wb[(size_t)j3 * 128 + tid]);
        accx = fmaf(w0, f0.x, accx); accy = fmaf(w0, f0.y, accy);
        accx = fmaf(w1, f1.x, accx); accy = fmaf(w1, f1.y, accy);
        accx = fmaf(w2, f2.x, accx); accy = fmaf(w2, f2.y, accy);
        accx = fmaf(w3, f3.x, accx); accy = fmaf(w3, f3.y, accy);
    }
    for (; p < c; ++p) {
        float2 f = __half22float2(Wb[(size_t)s_idx[p] * 128 + tid]);
        accx = fmaf(s_x[p], f.x, accx);
        accy = fmaf(s_x[p], f.y, accy);
    }
    accx *= Zi; accy *= Zi;
    float2 r;
    r.x = (accx > 0.0f) ? accx : expm1f(accx);   // elu
    r.y = (accy > 0.0f) ? accy : expm1f(accy);
    ((float2*)out)[(size_t)bi * 128 + tid] = r;
}

// ---------------------------------------------------------------------------
extern "C" void kernel_launch(void* const* d_in, const int* in_sizes, int n_in,
                              void* d_out, int out_size)
{
    const float* inp = (const float*)d_in[0];   // [B,N,H]
    const float* A   = (const float*)d_in[1];   // [B,N,N]
    const int*   l   = (const int*)  d_in[2];   // [B,2]
    const float* Wi  = (const float*)d_in[3];   // [H,H]
    const float* Wc  = (const float*)d_in[4];   // [H,H]
    const float* a   = (const float*)d_in[5];   // [2H,1]
    float* out = (float*)d_out;

    cudaFuncSetAttribute(gemm_kernel, cudaFuncAttributeMaxDynamicSharedMemorySize, SMEM_TOT);

    wsplit_kernel<<<2 * HH * HH / 256, 256>>>(Wi, Wc);
    gemm_kernel<<<BB * NN / 128, 512, SMEM_TOT>>>(inp, l, a);
    attn_kernel<<<BB * NN, 128>>>(A, out);
}

// round 9
// speedup vs baseline: 1.9964x; 1.0270x over previous
#include <cuda_runtime.h>
#include <cuda_fp16.h>
#include <cuda_bf16.h>
#include <math.h>
#include <stdint.h>

#define BB 32
#define NN 1024
#define HH 256

// Scratch (__device__ globals; no allocations allowed)
static __device__ __half        g_WhH[BB * NN * HH];   // 16 MB fp16 Wh
static __device__ __half        g_att[BB * NN * NN];   // 64 MB fp16 dense normalized att
static __device__ float         g_s1[BB * NN];
static __device__ float         g_s2[BB * NN];
static __device__ __nv_bfloat16 g_WT[4][HH * HH];      // WiH, WiL, WcH, WcL, transposed [n][k]

// ---------------------------------------------------------------------------
__device__ __forceinline__ uint32_t smem_u32(const void* p) {
    uint32_t a;
    asm("{ .reg .u64 t; cvta.to.shared.u64 t, %1; cvt.u32.u64 %0, t; }" : "=r"(a) : "l"(p));
    return a;
}

#define LDSM_X4(r0, r1, r2, r3, addr) \
    asm volatile("ldmatrix.sync.aligned.m8n8.x4.shared.b16 {%0,%1,%2,%3}, [%4];" \
                 : "=r"(r0), "=r"(r1), "=r"(r2), "=r"(r3) : "r"(addr))

#define LDSM_X4_T(r0, r1, r2, r3, addr) \
    asm volatile("ldmatrix.sync.aligned.m8n8.x4.trans.shared.b16 {%0,%1,%2,%3}, [%4];" \
                 : "=r"(r0), "=r"(r1), "=r"(r2), "=r"(r3) : "r"(addr))

#define MMA_BF16(d, a, b0r, b1r) \
    asm volatile("mma.sync.aligned.m16n8k16.row.col.f32.bf16.bf16.f32 " \
                 "{%0,%1,%2,%3}, {%4,%5,%6,%7}, {%8,%9}, {%0,%1,%2,%3};" \
                 : "+f"((d)[0]), "+f"((d)[1]), "+f"((d)[2]), "+f"((d)[3]) \
                 : "r"((a)[0]), "r"((a)[1]), "r"((a)[2]), "r"((a)[3]), \
                   "r"(b0r), "r"(b1r))

#define MMA_F16(d, a, b0r, b1r) \
    asm volatile("mma.sync.aligned.m16n8k16.row.col.f32.f16.f16.f32 " \
                 "{%0,%1,%2,%3}, {%4,%5,%6,%7}, {%8,%9}, {%0,%1,%2,%3};" \
                 : "+f"((d)[0]), "+f"((d)[1]), "+f"((d)[2]), "+f"((d)[3]) \
                 : "r"((a)[0]), "r"((a)[1]), "r"((a)[2]), "r"((a)[3]), \
                   "r"(b0r), "r"(b1r))

// ---------------------------------------------------------------------------
// Kernel 0: split W_i/W_c into transposed bf16 hi/lo: WT[n][k] = W[k][n]
// ---------------------------------------------------------------------------
__global__ __launch_bounds__(256) void wsplit_kernel(
    const float* __restrict__ Wi, const float* __restrict__ Wc)
{
    int idx = blockIdx.x * 256 + threadIdx.x;          // 0 .. 2*65536-1
    int which = idx >> 16;
    int e = idx & 65535;
    int n = e >> 8, k = e & 255;
    const float* W = which ? Wc : Wi;
    float x = W[k * HH + n];
    __nv_bfloat16 h = __float2bfloat16(x);
    __nv_bfloat16 lo = __float2bfloat16(x - __bfloat162float(h));
    g_WT[which * 2][n * HH + k] = h;
    g_WT[which * 2 + 1][n * HH + k] = lo;
}

// ---------------------------------------------------------------------------
// Kernel 1 (r8-validated): mma.sync bf16 3-term split GEMM, 128x256 per CTA,
// 512 threads. Fused s1/s2 dots + fp16 Wh store. Masks use WITHIN-BATCH index.
// ---------------------------------------------------------------------------
#define PADK 40
#define OFF_A   0
#define OFF_B   (2 * 128 * PADK * 2)
#define OFF_AV  (OFF_B + 2 * 256 * PADK * 2)
#define OFF_RED (OFF_AV + 512 * 4)
#define SMEM_TOT (OFF_RED + 4 * 128 * 2 * 4)

__global__ __launch_bounds__(512) void gemm_kernel(
    const float* __restrict__ inp, const int* __restrict__ l,
    const float* __restrict__ avec)
{
    extern __shared__ char smem[];
    const uint32_t sbA = smem_u32(smem) + OFF_A;
    const uint32_t sbB = smem_u32(smem) + OFF_B;
    float* sAv  = (float*)(smem + OFF_AV);
    float* sRed = (float*)(smem + OFF_RED);

    const int tid = threadIdx.x, lane = tid & 31, wid = tid >> 5;
    const int warpRow = wid >> 2, warpCol = wid & 3;
    const int rowTile = blockIdx.x * 128;
    const int b = rowTile >> 10;
    const int n0 = rowTile & 1023;
    const int l0 = l[2 * b], l1 = l[2 * b + 1];
    const bool mixed = (l0 > n0 && l0 < n0 + 128) || (l1 > n0 && l1 < n0 + 128);
    const bool sel0  = (n0 >= l0 && n0 < l1);
    const int npass  = mixed ? 2 : 1;

    sAv[tid] = avec[tid];

    for (int pass = 0; pass < npass; ++pass) {
        const bool useWi = mixed ? (pass == 0) : sel0;
        const __nv_bfloat16* __restrict__ Bh = g_WT[useWi ? 0 : 2];
        const __nv_bfloat16* __restrict__ Bl = g_WT[useWi ? 1 : 3];

        float acc[2][8][4];
        #pragma unroll
        for (int mt = 0; mt < 2; ++mt)
            #pragma unroll
            for (int nt = 0; nt < 8; ++nt)
                #pragma unroll
                for (int e = 0; e < 4; ++e) acc[mt][nt][e] = 0.0f;

        for (int kc = 0; kc < 8; ++kc) {
            const int k0 = kc * 32;
            __syncthreads();
            #pragma unroll
            for (int it = 0; it < 2; ++it) {
                int f = tid + it * 512;
                int r = f >> 3, c4 = (f & 7) * 4;
                float4 v = *(const float4*)(inp + (size_t)(rowTile + r) * HH + k0 + c4);
                float xv[4] = {v.x, v.y, v.z, v.w};
                unsigned short h[4], q[4];
                #pragma unroll
                for (int e = 0; e < 4; ++e) {
                    __nv_bfloat16 bh = __float2bfloat16(xv[e]);
                    h[e] = __bfloat16_as_ushort(bh);
                    q[e] = __bfloat16_as_ushort(
                        __float2bfloat16(xv[e] - __bfloat162float(bh)));
                }
                uint2 hv = make_uint2(h[0] | ((uint32_t)h[1] << 16),
                                      h[2] | ((uint32_t)h[3] << 16));
                uint2 lv = make_uint2(q[0] | ((uint32_t)q[1] << 16),
                                      q[2] | ((uint32_t)q[3] << 16));
                *(uint2*)(smem + OFF_A + ((size_t)r * PADK + c4) * 2) = hv;
                *(uint2*)(smem + OFF_A + ((size_t)(128 + r) * PADK + c4) * 2) = lv;
            }
            #pragma unroll
            for (int it = 0; it < 2; ++it) {
                int gI = tid + it * 512;
                int r = gI >> 2, c8 = (gI & 3) * 8;
                int4 vh = *(const int4*)(Bh + (size_t)r * HH + k0 + c8);
                int4 vl = *(const int4*)(Bl + (size_t)r * HH + k0 + c8);
                *(int4*)(smem + OFF_B + ((size_t)r * PADK + c8) * 2) = vh;
                *(int4*)(smem + OFF_B + ((size_t)(256 + r) * PADK + c8) * 2) = vl;
            }
            __syncthreads();

            #pragma unroll
            for (int ks = 0; ks < 2; ++ks) {
                const int kk = ks * 16;
                uint32_t ah[2][4], al[2][4];
                #pragma unroll
                for (int mt = 0; mt < 2; ++mt) {
                    int row = warpRow * 32 + mt * 16 + (lane & 15);
                    int kcol = kk + (lane >> 4) * 8;
                    uint32_t ad = sbA + (uint32_t)(row * PADK + kcol) * 2;
                    LDSM_X4(ah[mt][0], ah[mt][1], ah[mt][2], ah[mt][3], ad);
                    LDSM_X4(al[mt][0], al[mt][1], al[mt][2], al[mt][3],
                            ad + 128 * PADK * 2);
                }
                #pragma unroll
                for (int p = 0; p < 4; ++p) {
                    int row = warpCol * 64 + p * 16 + (lane & 7) + ((lane >> 4) << 3);
                    int kcol = kk + (((lane >> 3) & 1) << 3);
                    uint32_t bd = sbB + (uint32_t)(row * PADK + kcol) * 2;
                    uint32_t bh[4], bl[4];
                    LDSM_X4(bh[0], bh[1], bh[2], bh[3], bd);
                    LDSM_X4(bl[0], bl[1], bl[2], bl[3], bd + 256 * PADK * 2);
                    #pragma unroll
                    for (int mt = 0; mt < 2; ++mt) {
                        MMA_BF16(acc[mt][2 * p],     ah[mt], bh[0], bh[1]);
                        MMA_BF16(acc[mt][2 * p],     al[mt], bh[0], bh[1]);
                        MMA_BF16(acc[mt][2 * p],     ah[mt], bl[0], bl[1]);
                        MMA_BF16(acc[mt][2 * p + 1], ah[mt], bh[2], bh[3]);
                        MMA_BF16(acc[mt][2 * p + 1], al[mt], bh[2], bh[3]);
                        MMA_BF16(acc[mt][2 * p + 1], ah[mt], bl[2], bl[3]);
                    }
                }
            }
        }

        // ---- epilogue: fp16 Wh store + fused s1/s2 dots ----
        __syncthreads();
        const int g = lane >> 2, qc = (lane & 3) * 2;
        #pragma unroll
        for (int mt = 0; mt < 2; ++mt) {
            int lr0 = warpRow * 32 + mt * 16 + g;
            int lr1 = lr0 + 8;
            int gr0 = rowTile + lr0, gr1 = rowTile + lr1;   // global (addressing)
            int nr0 = n0 + lr0, nr1 = n0 + lr1;             // within-batch (masking)
            bool dw0 = !mixed || (((nr0 >= l0) && (nr0 < l1)) == useWi);
            bool dw1 = !mixed || (((nr1 >= l0) && (nr1 < l1)) == useWi);
            float s1r0 = 0, s2r0 = 0, s1r1 = 0, s2r1 = 0;
            #pragma unroll
            for (int nt = 0; nt < 8; ++nt) {
                int col = warpCol * 64 + nt * 8 + qc;
                float a0 = sAv[col], a1 = sAv[col + 1];
                float b0 = sAv[256 + col], b1 = sAv[256 + col + 1];
                float c0 = acc[mt][nt][0], c1 = acc[mt][nt][1];
                float c2 = acc[mt][nt][2], c3 = acc[mt][nt][3];
                s1r0 = fmaf(c0, a0, fmaf(c1, a1, s1r0));
                s2r0 = fmaf(c0, b0, fmaf(c1, b1, s2r0));
                s1r1 = fmaf(c2, a0, fmaf(c3, a1, s1r1));
                s2r1 = fmaf(c2, b0, fmaf(c3, b1, s2r1));
                if (dw0)
                    *(__half2*)(g_WhH + (size_t)gr0 * HH + col) = __floats2half2_rn(c0, c1);
                if (dw1)
                    *(__half2*)(g_WhH + (size_t)gr1 * HH + col) = __floats2half2_rn(c2, c3);
            }
            #pragma unroll
            for (int d = 1; d <= 2; d <<= 1) {
                s1r0 += __shfl_xor_sync(0xffffffffu, s1r0, d);
                s2r0 += __shfl_xor_sync(0xffffffffu, s2r0, d);
                s1r1 += __shfl_xor_sync(0xffffffffu, s1r1, d);
                s2r1 += __shfl_xor_sync(0xffffffffu, s2r1, d);
            }
            if ((lane & 3) == 0) {
                sRed[(warpCol * 128 + lr0) * 2 + 0] = s1r0;
                sRed[(warpCol * 128 + lr0) * 2 + 1] = s2r0;
                sRed[(warpCol * 128 + lr1) * 2 + 0] = s1r1;
                sRed[(warpCol * 128 + lr1) * 2 + 1] = s2r1;
            }
        }
        __syncthreads();
        if (tid < 128) {
            int grow = rowTile + tid;
            int nrow = n0 + tid;
            bool dw = !mixed || (((nrow >= l0) && (nrow < l1)) == useWi);
            if (dw) {
                float v1 = 0, v2 = 0;
                #pragma unroll
                for (int wc = 0; wc < 4; ++wc) {
                    v1 += sRed[(wc * 128 + tid) * 2 + 0];
                    v2 += sRed[(wc * 128 + tid) * 2 + 1];
                }
                g_s1[grow] = v1;
                g_s2[grow] = v2;
            }
        }
        __syncthreads();
    }
}

// ---------------------------------------------------------------------------
// Kernel 2: masked softmax scores -> dense fp16 normalized att row.
// Same math as the r8-passing attn phases A/B; no compaction, dense write.
// ---------------------------------------------------------------------------
__global__ __launch_bounds__(128) void score_kernel(
    const float* __restrict__ A, __half* __restrict__ att)
{
    __shared__ float s_red[8];

    const int bi = blockIdx.x;
    const int b = bi >> 10, i = bi & 1023;
    const int tid = threadIdx.x, lane = tid & 31, w = tid >> 5;
    const float* Arow = A + (size_t)bi * NN;
    const float* s2b = g_s2 + (size_t)b * NN;
    const float s1i = g_s1[bi];

    float av[8];
    {
        float4 v0 = *(const float4*)(Arow + tid * 8);
        float4 v1 = *(const float4*)(Arow + tid * 8 + 4);
        av[0] = v0.x; av[1] = v0.y; av[2] = v0.z; av[3] = v0.w;
        av[4] = v1.x; av[5] = v1.y; av[6] = v1.z; av[7] = v1.w;
    }
    unsigned pbits = 0;
    float xv[8];
    float lmax = -INFINITY;
    #pragma unroll
    for (int q = 0; q < 8; ++q) {
        int j = tid * 8 + q;
        float aval = av[q] + ((j == i) ? 1.0f : 0.0f);   // A + I (diag may be 2)
        if (aval > 0.0f) {
            float x = (s1i + s2b[j]) * aval;
            x = (x > 0.0f) ? x : 0.2f * x;               // leaky relu
            xv[q] = x;
            pbits |= (1u << q);
            lmax = fmaxf(lmax, x);
        }
    }
    float wm = lmax;
    #pragma unroll
    for (int d = 16; d > 0; d >>= 1) wm = fmaxf(wm, __shfl_xor_sync(0xffffffffu, wm, d));
    if (lane == 0) s_red[w] = wm;
    __syncthreads();
    const float m = fmaxf(fmaxf(s_red[0], s_red[1]), fmaxf(s_red[2], s_red[3]));

    float wv[8];
    float lz = 0.0f;
    #pragma unroll
    for (int q = 0; q < 8; ++q) {
        float e = (pbits & (1u << q)) ? expf(xv[q] - m) : 0.0f;
        wv[q] = e;
        lz += e;
    }
    #pragma unroll
    for (int d = 16; d > 0; d >>= 1) lz += __shfl_xor_sync(0xffffffffu, lz, d);
    if (lane == 0) s_red[4 + w] = lz;
    __syncthreads();
    const float Zi = 1.0f / (s_red[4] + s_red[5] + s_red[6] + s_red[7]);

    __half2 hv[4];
    #pragma unroll
    for (int q = 0; q < 4; ++q)
        hv[q] = __floats2half2_rn(wv[2 * q] * Zi, wv[2 * q + 1] * Zi);
    *(int4*)(att + (size_t)bi * NN + tid * 8) = *(const int4*)hv;
}

// ---------------------------------------------------------------------------
// Kernel 3: out = elu(att @ Wh), fp16 mma.sync, 128x256 tile per CTA,
// K=1024 in chunks of 32. Same fragment structure as gemm_kernel;
// B operand (Wh, [k][h] row-major) via ldmatrix.trans.
// ---------------------------------------------------------------------------
__global__ __launch_bounds__(512) void bmm_kernel(
    const __half* __restrict__ att, const __half* __restrict__ Wh,
    float* __restrict__ out)
{
    __shared__ __half sA[128][PADK];     // att tile [i][k]
    __shared__ __half sB[32][264];       // Wh tile  [k][h], pad 8

    const int tid = threadIdx.x, lane = tid & 31, wid = tid >> 5;
    const int warpRow = wid >> 2, warpCol = wid & 3;
    const int b  = blockIdx.x >> 3;
    const int rt = (blockIdx.x & 7) * 128;
    const __half* attB = att + ((size_t)b * NN + rt) * NN;
    const __half* WhB  = Wh + (size_t)b * NN * HH;

    const uint32_t sbA = smem_u32(&sA[0][0]);
    const uint32_t sbB = smem_u32(&sB[0][0]);

    float acc[2][8][4];
    #pragma unroll
    for (int mt = 0; mt < 2; ++mt)
        #pragma unroll
        for (int nt = 0; nt < 8; ++nt)
            #pragma unroll
            for (int e = 0; e < 4; ++e) acc[mt][nt][e] = 0.0f;

    const int ar = tid >> 2, ac8 = (tid & 3) * 8;       // att loader
    const int br = tid >> 4, bc16 = (tid & 15) * 16;    // Wh loader

    for (int k0 = 0; k0 < NN; k0 += 32) {
        __syncthreads();
        // att tile 128x32 fp16 (one int4 per thread)
        *(int4*)&sA[ar][ac8] = *(const int4*)(attB + (size_t)ar * NN + k0 + ac8);
        // Wh tile 32x256 fp16 (two int4 per thread)
        *(int4*)&sB[br][bc16]     = *(const int4*)(WhB + (size_t)(k0 + br) * HH + bc16);
        *(int4*)&sB[br][bc16 + 8] = *(const int4*)(WhB + (size_t)(k0 + br) * HH + bc16 + 8);
        __syncthreads();

        #pragma unroll
        for (int ks = 0; ks < 2; ++ks) {
            const int kk = ks * 16;
            uint32_t a[2][4];
            #pragma unroll
            for (int mt = 0; mt < 2; ++mt) {
                int row = warpRow * 32 + mt * 16 + (lane & 15);
                int kcol = kk + (lane >> 4) * 8;
                LDSM_X4(a[mt][0], a[mt][1], a[mt][2], a[mt][3],
                        sbA + (uint32_t)(row * PADK + kcol) * 2);
            }
            #pragma unroll
            for (int p = 0; p < 4; ++p) {
                int n = warpCol * 64 + p * 16;
                int krow = kk + (lane & 15);
                int col = n + ((lane >> 4) << 3);
                uint32_t bfr[4];
                LDSM_X4_T(bfr[0], bfr[1], bfr[2], bfr[3],
                          sbB + (uint32_t)(krow * 264 + col) * 2);
                #pragma unroll
                for (int mt = 0; mt < 2; ++mt) {
                    MMA_F16(acc[mt][2 * p],     a[mt], bfr[0], bfr[1]);
                    MMA_F16(acc[mt][2 * p + 1], a[mt], bfr[2], bfr[3]);
                }
            }
        }
    }

    // ---- epilogue: elu + fp32 store ----
    const int g = lane >> 2, qc = (lane & 3) * 2;
    #pragma unroll
    for (int mt = 0; mt < 2; ++mt) {
        int lr0 = warpRow * 32 + mt * 16 + g;
        int lr1 = lr0 + 8;
        size_t o0 = ((size_t)b * NN + rt + lr0) * HH;
        size_t o1 = ((size_t)b * NN + rt + lr1) * HH;
        #pragma unroll
        for (int nt = 0; nt < 8; ++nt) {
            int col = warpCol * 64 + nt * 8 + qc;
            float c0 = acc[mt][nt][0], c1 = acc[mt][nt][1];
            float c2 = acc[mt][nt][2], c3 = acc[mt][nt][3];
            float2 r0, r1;
            r0.x = (c0 > 0.0f) ? c0 : expm1f(c0);
            r0.y = (c1 > 0.0f) ? c1 : expm1f(c1);
            r1.x = (c2 > 0.0f) ? c2 : expm1f(c2);
            r1.y = (c3 > 0.0f) ? c3 : expm1f(c3);
            *(float2*)(out + o0 + col) = r0;
            *(float2*)(out + o1 + col) = r1;
        }
    }
}

// ---------------------------------------------------------------------------
extern "C" void kernel_launch(void* const* d_in, const int* in_sizes, int n_in,
                              void* d_out, int out_size)
{
    const float* inp = (const float*)d_in[0];   // [B,N,H]
    const float* A   = (const float*)d_in[1];   // [B,N,N]
    const int*   l   = (const int*)  d_in[2];   // [B,2]
    const float* Wi  = (const float*)d_in[3];   // [H,H]
    const float* Wc  = (const float*)d_in[4];   // [H,H]
    const float* a   = (const float*)d_in[5];   // [2H,1]
    float* out = (float*)d_out;

    __half *WhH, *att;
    cudaGetSymbolAddress((void**)&WhH, g_WhH);
    cudaGetSymbolAddress((void**)&att, g_att);

    cudaFuncSetAttribute(gemm_kernel, cudaFuncAttributeMaxDynamicSharedMemorySize, SMEM_TOT);

    wsplit_kernel<<<2 * HH * HH / 256, 256>>>(Wi, Wc);
    gemm_kernel<<<BB * NN / 128, 512, SMEM_TOT>>>(inp, l, a);
    score_kernel<<<BB * NN, 128>>>(A, att);
    bmm_kernel<<<BB * NN / 128, 512>>>(att, WhH, out);
}

// round 10
// speedup vs baseline: 2.2768x; 1.1404x over previous
#include <cuda_runtime.h>
#include <cuda_fp16.h>
#include <cuda_bf16.h>
#include <math.h>
#include <stdint.h>

#define BB 32
#define NN 1024
#define HH 256

// Scratch (__device__ globals; no allocations allowed)
static __device__ __half        g_WhH[BB * NN * HH];   // 16 MB fp16 Wh
static __device__ __half        g_att[BB * NN * NN];   // 64 MB fp16 dense normalized att
static __device__ float         g_s1[BB * NN];
static __device__ float         g_s2[BB * NN];
static __device__ __nv_bfloat16 g_WT[4][HH * HH];      // WiH, WiL, WcH, WcL, transposed [n][k]

// ---------------------------------------------------------------------------
__device__ __forceinline__ uint32_t smem_u32(const void* p) {
    uint32_t a;
    asm("{ .reg .u64 t; cvta.to.shared.u64 t, %1; cvt.u32.u64 %0, t; }" : "=r"(a) : "l"(p));
    return a;
}

#define LDSM_X4(r0, r1, r2, r3, addr) \
    asm volatile("ldmatrix.sync.aligned.m8n8.x4.shared.b16 {%0,%1,%2,%3}, [%4];" \
                 : "=r"(r0), "=r"(r1), "=r"(r2), "=r"(r3) : "r"(addr))

#define LDSM_X4_T(r0, r1, r2, r3, addr) \
    asm volatile("ldmatrix.sync.aligned.m8n8.x4.trans.shared.b16 {%0,%1,%2,%3}, [%4];" \
                 : "=r"(r0), "=r"(r1), "=r"(r2), "=r"(r3) : "r"(addr))

#define MMA_BF16(d, a, b0r, b1r) \
    asm volatile("mma.sync.aligned.m16n8k16.row.col.f32.bf16.bf16.f32 " \
                 "{%0,%1,%2,%3}, {%4,%5,%6,%7}, {%8,%9}, {%0,%1,%2,%3};" \
                 : "+f"((d)[0]), "+f"((d)[1]), "+f"((d)[2]), "+f"((d)[3]) \
                 : "r"((a)[0]), "r"((a)[1]), "r"((a)[2]), "r"((a)[3]), \
                   "r"(b0r), "r"(b1r))

#define MMA_F16(d, a, b0r, b1r) \
    asm volatile("mma.sync.aligned.m16n8k16.row.col.f32.f16.f16.f32 " \
                 "{%0,%1,%2,%3}, {%4,%5,%6,%7}, {%8,%9}, {%0,%1,%2,%3};" \
                 : "+f"((d)[0]), "+f"((d)[1]), "+f"((d)[2]), "+f"((d)[3]) \
                 : "r"((a)[0]), "r"((a)[1]), "r"((a)[2]), "r"((a)[3]), \
                   "r"(b0r), "r"(b1r))

#define CP16(dst, src) \
    asm volatile("cp.async.cg.shared.global [%0], [%1], 16;" :: "r"(dst), "l"(src))
#define CP_COMMIT() asm volatile("cp.async.commit_group;" ::: "memory")

// ---------------------------------------------------------------------------
// Kernel 0: split W_i/W_c into transposed bf16 hi/lo: WT[n][k] = W[k][n]
// ---------------------------------------------------------------------------
__global__ __launch_bounds__(256) void wsplit_kernel(
    const float* __restrict__ Wi, const float* __restrict__ Wc)
{
    int idx = blockIdx.x * 256 + threadIdx.x;          // 0 .. 2*65536-1
    int which = idx >> 16;
    int e = idx & 65535;
    int n = e >> 8, k = e & 255;
    const float* W = which ? Wc : Wi;
    float x = W[k * HH + n];
    __nv_bfloat16 h = __float2bfloat16(x);
    __nv_bfloat16 lo = __float2bfloat16(x - __bfloat162float(h));
    g_WT[which * 2][n * HH + k] = h;
    g_WT[which * 2 + 1][n * HH + k] = lo;
}

// ---------------------------------------------------------------------------
// Kernel 1 (r8-validated, unchanged): mma.sync bf16 3-term split GEMM,
// 128x256 per CTA, 512 threads. Fused s1/s2 dots + fp16 Wh store.
// ---------------------------------------------------------------------------
#define PADK 40
#define OFF_A   0
#define OFF_B   (2 * 128 * PADK * 2)
#define OFF_AV  (OFF_B + 2 * 256 * PADK * 2)
#define OFF_RED (OFF_AV + 512 * 4)
#define SMEM_TOT (OFF_RED + 4 * 128 * 2 * 4)

__global__ __launch_bounds__(512) void gemm_kernel(
    const float* __restrict__ inp, const int* __restrict__ l,
    const float* __restrict__ avec)
{
    extern __shared__ char smem[];
    const uint32_t sbA = smem_u32(smem) + OFF_A;
    const uint32_t sbB = smem_u32(smem) + OFF_B;
    float* sAv  = (float*)(smem + OFF_AV);
    float* sRed = (float*)(smem + OFF_RED);

    const int tid = threadIdx.x, lane = tid & 31, wid = tid >> 5;
    const int warpRow = wid >> 2, warpCol = wid & 3;
    const int rowTile = blockIdx.x * 128;
    const int b = rowTile >> 10;
    const int n0 = rowTile & 1023;
    const int l0 = l[2 * b], l1 = l[2 * b + 1];
    const bool mixed = (l0 > n0 && l0 < n0 + 128) || (l1 > n0 && l1 < n0 + 128);
    const bool sel0  = (n0 >= l0 && n0 < l1);
    const int npass  = mixed ? 2 : 1;

    sAv[tid] = avec[tid];

    for (int pass = 0; pass < npass; ++pass) {
        const bool useWi = mixed ? (pass == 0) : sel0;
        const __nv_bfloat16* __restrict__ Bh = g_WT[useWi ? 0 : 2];
        const __nv_bfloat16* __restrict__ Bl = g_WT[useWi ? 1 : 3];

        float acc[2][8][4];
        #pragma unroll
        for (int mt = 0; mt < 2; ++mt)
            #pragma unroll
            for (int nt = 0; nt < 8; ++nt)
                #pragma unroll
                for (int e = 0; e < 4; ++e) acc[mt][nt][e] = 0.0f;

        for (int kc = 0; kc < 8; ++kc) {
            const int k0 = kc * 32;
            __syncthreads();
            #pragma unroll
            for (int it = 0; it < 2; ++it) {
                int f = tid + it * 512;
                int r = f >> 3, c4 = (f & 7) * 4;
                float4 v = *(const float4*)(inp + (size_t)(rowTile + r) * HH + k0 + c4);
                float xv[4] = {v.x, v.y, v.z, v.w};
                unsigned short h[4], q[4];
                #pragma unroll
                for (int e = 0; e < 4; ++e) {
                    __nv_bfloat16 bh = __float2bfloat16(xv[e]);
                    h[e] = __bfloat16_as_ushort(bh);
                    q[e] = __bfloat16_as_ushort(
                        __float2bfloat16(xv[e] - __bfloat162float(bh)));
                }
                uint2 hv = make_uint2(h[0] | ((uint32_t)h[1] << 16),
                                      h[2] | ((uint32_t)h[3] << 16));
                uint2 lv = make_uint2(q[0] | ((uint32_t)q[1] << 16),
                                      q[2] | ((uint32_t)q[3] << 16));
                *(uint2*)(smem + OFF_A + ((size_t)r * PADK + c4) * 2) = hv;
                *(uint2*)(smem + OFF_A + ((size_t)(128 + r) * PADK + c4) * 2) = lv;
            }
            #pragma unroll
            for (int it = 0; it < 2; ++it) {
                int gI = tid + it * 512;
                int r = gI >> 2, c8 = (gI & 3) * 8;
                int4 vh = *(const int4*)(Bh + (size_t)r * HH + k0 + c8);
                int4 vl = *(const int4*)(Bl + (size_t)r * HH + k0 + c8);
                *(int4*)(smem + OFF_B + ((size_t)r * PADK + c8) * 2) = vh;
                *(int4*)(smem + OFF_B + ((size_t)(256 + r) * PADK + c8) * 2) = vl;
            }
            __syncthreads();

            #pragma unroll
            for (int ks = 0; ks < 2; ++ks) {
                const int kk = ks * 16;
                uint32_t ah[2][4], al[2][4];
                #pragma unroll
                for (int mt = 0; mt < 2; ++mt) {
                    int row = warpRow * 32 + mt * 16 + (lane & 15);
                    int kcol = kk + (lane >> 4) * 8;
                    uint32_t ad = sbA + (uint32_t)(row * PADK + kcol) * 2;
                    LDSM_X4(ah[mt][0], ah[mt][1], ah[mt][2], ah[mt][3], ad);
                    LDSM_X4(al[mt][0], al[mt][1], al[mt][2], al[mt][3],
                            ad + 128 * PADK * 2);
                }
                #pragma unroll
                for (int p = 0; p < 4; ++p) {
                    int row = warpCol * 64 + p * 16 + (lane & 7) + ((lane >> 4) << 3);
                    int kcol = kk + (((lane >> 3) & 1) << 3);
                    uint32_t bd = sbB + (uint32_t)(row * PADK + kcol) * 2;
                    uint32_t bh[4], bl[4];
                    LDSM_X4(bh[0], bh[1], bh[2], bh[3], bd);
                    LDSM_X4(bl[0], bl[1], bl[2], bl[3], bd + 256 * PADK * 2);
                    #pragma unroll
                    for (int mt = 0; mt < 2; ++mt) {
                        MMA_BF16(acc[mt][2 * p],     ah[mt], bh[0], bh[1]);
                        MMA_BF16(acc[mt][2 * p],     al[mt], bh[0], bh[1]);
                        MMA_BF16(acc[mt][2 * p],     ah[mt], bl[0], bl[1]);
                        MMA_BF16(acc[mt][2 * p + 1], ah[mt], bh[2], bh[3]);
                        MMA_BF16(acc[mt][2 * p + 1], al[mt], bh[2], bh[3]);
                        MMA_BF16(acc[mt][2 * p + 1], ah[mt], bl[2], bl[3]);
                    }
                }
            }
        }

        // ---- epilogue: fp16 Wh store + fused s1/s2 dots ----
        __syncthreads();
        const int g = lane >> 2, qc = (lane & 3) * 2;
        #pragma unroll
        for (int mt = 0; mt < 2; ++mt) {
            int lr0 = warpRow * 32 + mt * 16 + g;
            int lr1 = lr0 + 8;
            int gr0 = rowTile + lr0, gr1 = rowTile + lr1;   // global (addressing)
            int nr0 = n0 + lr0, nr1 = n0 + lr1;             // within-batch (masking)
            bool dw0 = !mixed || (((nr0 >= l0) && (nr0 < l1)) == useWi);
            bool dw1 = !mixed || (((nr1 >= l0) && (nr1 < l1)) == useWi);
            float s1r0 = 0, s2r0 = 0, s1r1 = 0, s2r1 = 0;
            #pragma unroll
            for (int nt = 0; nt < 8; ++nt) {
                int col = warpCol * 64 + nt * 8 + qc;
                float a0 = sAv[col], a1 = sAv[col + 1];
                float b0 = sAv[256 + col], b1 = sAv[256 + col + 1];
                float c0 = acc[mt][nt][0], c1 = acc[mt][nt][1];
                float c2 = acc[mt][nt][2], c3 = acc[mt][nt][3];
                s1r0 = fmaf(c0, a0, fmaf(c1, a1, s1r0));
                s2r0 = fmaf(c0, b0, fmaf(c1, b1, s2r0));
                s1r1 = fmaf(c2, a0, fmaf(c3, a1, s1r1));
                s2r1 = fmaf(c2, b0, fmaf(c3, b1, s2r1));
                if (dw0)
                    *(__half2*)(g_WhH + (size_t)gr0 * HH + col) = __floats2half2_rn(c0, c1);
                if (dw1)
                    *(__half2*)(g_WhH + (size_t)gr1 * HH + col) = __floats2half2_rn(c2, c3);
            }
            #pragma unroll
            for (int d = 1; d <= 2; d <<= 1) {
                s1r0 += __shfl_xor_sync(0xffffffffu, s1r0, d);
                s2r0 += __shfl_xor_sync(0xffffffffu, s2r0, d);
                s1r1 += __shfl_xor_sync(0xffffffffu, s1r1, d);
                s2r1 += __shfl_xor_sync(0xffffffffu, s2r1, d);
            }
            if ((lane & 3) == 0) {
                sRed[(warpCol * 128 + lr0) * 2 + 0] = s1r0;
                sRed[(warpCol * 128 + lr0) * 2 + 1] = s2r0;
                sRed[(warpCol * 128 + lr1) * 2 + 0] = s1r1;
                sRed[(warpCol * 128 + lr1) * 2 + 1] = s2r1;
            }
        }
        __syncthreads();
        if (tid < 128) {
            int grow = rowTile + tid;
            int nrow = n0 + tid;
            bool dw = !mixed || (((nrow >= l0) && (nrow < l1)) == useWi);
            if (dw) {
                float v1 = 0, v2 = 0;
                #pragma unroll
                for (int wc = 0; wc < 4; ++wc) {
                    v1 += sRed[(wc * 128 + tid) * 2 + 0];
                    v2 += sRed[(wc * 128 + tid) * 2 + 1];
                }
                g_s1[grow] = v1;
                g_s2[grow] = v2;
            }
        }
        __syncthreads();
    }
}

// ---------------------------------------------------------------------------
// Kernel 2 (unchanged): masked softmax -> dense fp16 normalized att row.
// ---------------------------------------------------------------------------
__global__ __launch_bounds__(128) void score_kernel(
    const float* __restrict__ A, __half* __restrict__ att)
{
    __shared__ float s_red[8];

    const int bi = blockIdx.x;
    const int b = bi >> 10, i = bi & 1023;
    const int tid = threadIdx.x, lane = tid & 31, w = tid >> 5;
    const float* Arow = A + (size_t)bi * NN;
    const float* s2b = g_s2 + (size_t)b * NN;
    const float s1i = g_s1[bi];

    float av[8];
    {
        float4 v0 = *(const float4*)(Arow + tid * 8);
        float4 v1 = *(const float4*)(Arow + tid * 8 + 4);
        av[0] = v0.x; av[1] = v0.y; av[2] = v0.z; av[3] = v0.w;
        av[4] = v1.x; av[5] = v1.y; av[6] = v1.z; av[7] = v1.w;
    }
    unsigned pbits = 0;
    float xv[8];
    float lmax = -INFINITY;
    #pragma unroll
    for (int q = 0; q < 8; ++q) {
        int j = tid * 8 + q;
        float aval = av[q] + ((j == i) ? 1.0f : 0.0f);   // A + I (diag may be 2)
        if (aval > 0.0f) {
            float x = (s1i + s2b[j]) * aval;
            x = (x > 0.0f) ? x : 0.2f * x;               // leaky relu
            xv[q] = x;
            pbits |= (1u << q);
            lmax = fmaxf(lmax, x);
        }
    }
    float wm = lmax;
    #pragma unroll
    for (int d = 16; d > 0; d >>= 1) wm = fmaxf(wm, __shfl_xor_sync(0xffffffffu, wm, d));
    if (lane == 0) s_red[w] = wm;
    __syncthreads();
    const float m = fmaxf(fmaxf(s_red[0], s_red[1]), fmaxf(s_red[2], s_red[3]));

    float wv[8];
    float lz = 0.0f;
    #pragma unroll
    for (int q = 0; q < 8; ++q) {
        float e = (pbits & (1u << q)) ? expf(xv[q] - m) : 0.0f;
        wv[q] = e;
        lz += e;
    }
    #pragma unroll
    for (int d = 16; d > 0; d >>= 1) lz += __shfl_xor_sync(0xffffffffu, lz, d);
    if (lane == 0) s_red[4 + w] = lz;
    __syncthreads();
    const float Zi = 1.0f / (s_red[4] + s_red[5] + s_red[6] + s_red[7]);

    __half2 hv[4];
    #pragma unroll
    for (int q = 0; q < 4; ++q)
        hv[q] = __floats2half2_rn(wv[2 * q] * Zi, wv[2 * q + 1] * Zi);
    *(int4*)(att + (size_t)bi * NN + tid * 8) = *(const int4*)hv;
}

// ---------------------------------------------------------------------------
// Kernel 3 v2: out = elu(att @ Wh), fp16 mma.sync, 128x256 tile per CTA.
// 2-stage cp.async double-buffered pipeline, K-chunk 64 (16 iterations).
// Fragment/ldmatrix/mma code identical to the validated r9 version.
// ---------------------------------------------------------------------------
#define BPADK 72                                   // A stage k-stride (halves)
#define BOFF_B (2 * 128 * BPADK * 2)               // 36864
#define BSMEM_TOT (BOFF_B + 2 * 64 * 264 * 2)      // 104448

__global__ __launch_bounds__(512) void bmm_kernel(
    const __half* __restrict__ att, const __half* __restrict__ Wh,
    float* __restrict__ out)
{
    extern __shared__ char bsm[];
    const uint32_t aBase = smem_u32(bsm);
    const uint32_t bBase = aBase + BOFF_B;

    const int tid = threadIdx.x, lane = tid & 31, wid = tid >> 5;
    const int warpRow = wid >> 2, warpCol = wid & 3;
    const int b  = blockIdx.x >> 3;
    const int rt = (blockIdx.x & 7) * 128;
    const __half* attB = att + ((size_t)b * NN + rt) * NN;
    const __half* WhB  = Wh + (size_t)b * NN * HH;

    float acc[2][8][4];
    #pragma unroll
    for (int mt = 0; mt < 2; ++mt)
        #pragma unroll
        for (int nt = 0; nt < 8; ++nt)
            #pragma unroll
            for (int e = 0; e < 4; ++e) acc[mt][nt][e] = 0.0f;

    // loader indices
    const int lar = tid >> 3, lac = (tid & 7) * 8;      // att: 2 iters cover 128x64
    const int lbr = tid >> 5, lbc = (tid & 31) * 8;     // Wh:  4 iters cover 64x256... (r via +16)

    // issue cp.async loads for k-chunk kc into stage s
    auto load_stage = [&](int kc, int s) {
        const int k0 = kc * 64;
        uint32_t aS = aBase + (uint32_t)s * 128 * BPADK * 2;
        uint32_t bS = bBase + (uint32_t)s * 64 * 264 * 2;
        #pragma unroll
        for (int it = 0; it < 2; ++it) {
            int f = tid + it * 512;                 // 0..1023
            int r = f >> 3, c = (f & 7) * 8;        // 128 rows x 8 segs
            CP16(aS + (uint32_t)(r * BPADK + c) * 2,
                 attB + (size_t)r * NN + k0 + c);
        }
        #pragma unroll
        for (int it = 0; it < 4; ++it) {
            int f = tid + it * 512;                 // 0..2047
            int r = f >> 5, c = (f & 31) * 8;       // 64 rows x 32 segs
            CP16(bS + (uint32_t)(r * 264 + c) * 2,
                 WhB + (size_t)(k0 + r) * HH + c);
        }
        CP_COMMIT();
    };

    load_stage(0, 0);

    for (int kc = 0; kc < 16; ++kc) {
        const int s = kc & 1;
        if (kc + 1 < 16) {
            load_stage(kc + 1, s ^ 1);
            asm volatile("cp.async.wait_group 1;" ::: "memory");
        } else {
            asm volatile("cp.async.wait_group 0;" ::: "memory");
        }
        __syncthreads();

        const uint32_t aS = aBase + (uint32_t)s * 128 * BPADK * 2;
        const uint32_t bS = bBase + (uint32_t)s * 64 * 264 * 2;
        #pragma unroll
        for (int ks = 0; ks < 4; ++ks) {
            const int kk = ks * 16;
            uint32_t a[2][4];
            #pragma unroll
            for (int mt = 0; mt < 2; ++mt) {
                int row = warpRow * 32 + mt * 16 + (lane & 15);
                int kcol = kk + (lane >> 4) * 8;
                LDSM_X4(a[mt][0], a[mt][1], a[mt][2], a[mt][3],
                        aS + (uint32_t)(row * BPADK + kcol) * 2);
            }
            #pragma unroll
            for (int p = 0; p < 4; ++p) {
                int n = warpCol * 64 + p * 16;
                int krow = kk + (lane & 15);
                int col = n + ((lane >> 4) << 3);
                uint32_t bfr[4];
                LDSM_X4_T(bfr[0], bfr[1], bfr[2], bfr[3],
                          bS + (uint32_t)(krow * 264 + col) * 2);
                #pragma unroll
                for (int mt = 0; mt < 2; ++mt) {
                    MMA_F16(acc[mt][2 * p],     a[mt], bfr[0], bfr[1]);
                    MMA_F16(acc[mt][2 * p + 1], a[mt], bfr[2], bfr[3]);
                }
            }
        }
        __syncthreads();   // stage s free for reuse at kc+2
    }

    // ---- epilogue: elu + fp32 store ----
    const int g = lane >> 2, qc = (lane & 3) * 2;
    #pragma unroll
    for (int mt = 0; mt < 2; ++mt) {
        int lr0 = warpRow * 32 + mt * 16 + g;
        int lr1 = lr0 + 8;
        size_t o0 = ((size_t)b * NN + rt + lr0) * HH;
        size_t o1 = ((size_t)b * NN + rt + lr1) * HH;
        #pragma unroll
        for (int nt = 0; nt < 8; ++nt) {
            int col = warpCol * 64 + nt * 8 + qc;
            float c0 = acc[mt][nt][0], c1 = acc[mt][nt][1];
            float c2 = acc[mt][nt][2], c3 = acc[mt][nt][3];
            float2 r0, r1;
            r0.x = (c0 > 0.0f) ? c0 : expm1f(c0);
            r0.y = (c1 > 0.0f) ? c1 : expm1f(c1);
            r1.x = (c2 > 0.0f) ? c2 : expm1f(c2);
            r1.y = (c3 > 0.0f) ? c3 : expm1f(c3);
            *(float2*)(out + o0 + col) = r0;
            *(float2*)(out + o1 + col) = r1;
        }
    }
}

// ---------------------------------------------------------------------------
extern "C" void kernel_launch(void* const* d_in, const int* in_sizes, int n_in,
                              void* d_out, int out_size)
{
    const float* inp = (const float*)d_in[0];   // [B,N,H]
    const float* A   = (const float*)d_in[1];   // [B,N,N]
    const int*   l   = (const int*)  d_in[2];   // [B,2]
    const float* Wi  = (const float*)d_in[3];   // [H,H]
    const float* Wc  = (const float*)d_in[4];   // [H,H]
    const float* a   = (const float*)d_in[5];   // [2H,1]
    float* out = (float*)d_out;

    __half *WhH, *att;
    cudaGetSymbolAddress((void**)&WhH, g_WhH);
    cudaGetSymbolAddress((void**)&att, g_att);

    cudaFuncSetAttribute(gemm_kernel, cudaFuncAttributeMaxDynamicSharedMemorySize, SMEM_TOT);
    cudaFuncSetAttribute(bmm_kernel, cudaFuncAttributeMaxDynamicSharedMemorySize, BSMEM_TOT);

    wsplit_kernel<<<2 * HH * HH / 256, 256>>>(Wi, Wc);
    gemm_kernel<<<BB * NN / 128, 512, SMEM_TOT>>>(inp, l, a);
    score_kernel<<<BB * NN, 128>>>(A, att);
    bmm_kernel<<<BB * NN / 128, 512, BSMEM_TOT>>>(att, WhH, out);
}

// round 11
// speedup vs baseline: 2.3930x; 1.0510x over previous
#include <cuda_runtime.h>
#include <cuda_fp16.h>
#include <cuda_bf16.h>
#include <math.h>
#include <stdint.h>

#define BB 32
#define NN 1024
#define HH 256

// Scratch (__device__ globals; no allocations allowed)
static __device__ __half        g_WhH[BB * NN * HH];   // 16 MB fp16 Wh
static __device__ __half        g_att[BB * NN * NN];   // 64 MB fp16 dense normalized att
static __device__ float         g_s1[BB * NN];
static __device__ float         g_s2[BB * NN];
static __device__ __nv_bfloat16 g_WT[4][HH * HH];      // WiH, WiL, WcH, WcL, transposed [n][k]

// ---------------------------------------------------------------------------
__device__ __forceinline__ uint32_t smem_u32(const void* p) {
    uint32_t a;
    asm("{ .reg .u64 t; cvta.to.shared.u64 t, %1; cvt.u32.u64 %0, t; }" : "=r"(a) : "l"(p));
    return a;
}

#define LDSM_X4(r0, r1, r2, r3, addr) \
    asm volatile("ldmatrix.sync.aligned.m8n8.x4.shared.b16 {%0,%1,%2,%3}, [%4];" \
                 : "=r"(r0), "=r"(r1), "=r"(r2), "=r"(r3) : "r"(addr))

#define LDSM_X4_T(r0, r1, r2, r3, addr) \
    asm volatile("ldmatrix.sync.aligned.m8n8.x4.trans.shared.b16 {%0,%1,%2,%3}, [%4];" \
                 : "=r"(r0), "=r"(r1), "=r"(r2), "=r"(r3) : "r"(addr))

#define MMA_BF16(d, a, b0r, b1r) \
    asm volatile("mma.sync.aligned.m16n8k16.row.col.f32.bf16.bf16.f32 " \
                 "{%0,%1,%2,%3}, {%4,%5,%6,%7}, {%8,%9}, {%0,%1,%2,%3};" \
                 : "+f"((d)[0]), "+f"((d)[1]), "+f"((d)[2]), "+f"((d)[3]) \
                 : "r"((a)[0]), "r"((a)[1]), "r"((a)[2]), "r"((a)[3]), \
                   "r"(b0r), "r"(b1r))

#define MMA_F16(d, a, b0r, b1r) \
    asm volatile("mma.sync.aligned.m16n8k16.row.col.f32.f16.f16.f32 " \
                 "{%0,%1,%2,%3}, {%4,%5,%6,%7}, {%8,%9}, {%0,%1,%2,%3};" \
                 : "+f"((d)[0]), "+f"((d)[1]), "+f"((d)[2]), "+f"((d)[3]) \
                 : "r"((a)[0]), "r"((a)[1]), "r"((a)[2]), "r"((a)[3]), \
                   "r"(b0r), "r"(b1r))

#define CP16(dst, src) \
    asm volatile("cp.async.cg.shared.global [%0], [%1], 16;" :: "r"(dst), "l"(src))
#define CP_COMMIT() asm volatile("cp.async.commit_group;" ::: "memory")

// ---------------------------------------------------------------------------
// Kernel 0: split W_i/W_c into transposed bf16 hi/lo: WT[n][k] = W[k][n]
// ---------------------------------------------------------------------------
__global__ __launch_bounds__(256) void wsplit_kernel(
    const float* __restrict__ Wi, const float* __restrict__ Wc)
{
    int idx = blockIdx.x * 256 + threadIdx.x;          // 0 .. 2*65536-1
    int which = idx >> 16;
    int e = idx & 65535;
    int n = e >> 8, k = e & 255;
    const float* W = which ? Wc : Wi;
    float x = W[k * HH + n];
    __nv_bfloat16 h = __float2bfloat16(x);
    __nv_bfloat16 lo = __float2bfloat16(x - __bfloat162float(h));
    g_WT[which * 2][n * HH + k] = h;
    g_WT[which * 2 + 1][n * HH + k] = lo;
}

// ---------------------------------------------------------------------------
// Kernel 1: mma.sync bf16 3-term split GEMM, 128x256 per CTA, 512 threads.
// v2: double-buffered smem + register prefetch of next chunk's global loads.
// Compute fragments and epilogue identical to the r8-validated version.
// ---------------------------------------------------------------------------
#define PADK 40
#define ABUF (2 * 128 * PADK * 2)              // 20480 (hi+lo planes)
#define BBUF (2 * 256 * PADK * 2)              // 40960
#define OFF_A   0                              // stage s at s*ABUF
#define OFF_B   (2 * ABUF)                     // 40960; stage s at +s*BBUF
#define OFF_AV  (OFF_B + 2 * BBUF)             // 122880
#define OFF_RED (OFF_AV + 512 * 4)             // 124928
#define SMEM_TOT (OFF_RED + 4 * 128 * 2 * 4)   // 129024

__global__ __launch_bounds__(512) void gemm_kernel(
    const float* __restrict__ inp, const int* __restrict__ l,
    const float* __restrict__ avec)
{
    extern __shared__ char smem[];
    const uint32_t sbA = smem_u32(smem) + OFF_A;
    const uint32_t sbB = smem_u32(smem) + OFF_B;
    float* sAv  = (float*)(smem + OFF_AV);
    float* sRed = (float*)(smem + OFF_RED);

    const int tid = threadIdx.x, lane = tid & 31, wid = tid >> 5;
    const int warpRow = wid >> 2, warpCol = wid & 3;
    const int rowTile = blockIdx.x * 128;
    const int b = rowTile >> 10;
    const int n0 = rowTile & 1023;
    const int l0 = l[2 * b], l1 = l[2 * b + 1];
    const bool mixed = (l0 > n0 && l0 < n0 + 128) || (l1 > n0 && l1 < n0 + 128);
    const bool sel0  = (n0 >= l0 && n0 < l1);
    const int npass  = mixed ? 2 : 1;

    sAv[tid] = avec[tid];

    for (int pass = 0; pass < npass; ++pass) {
        const bool useWi = mixed ? (pass == 0) : sel0;
        const __nv_bfloat16* __restrict__ Bh = g_WT[useWi ? 0 : 2];
        const __nv_bfloat16* __restrict__ Bl = g_WT[useWi ? 1 : 3];

        float acc[2][8][4];
        #pragma unroll
        for (int mt = 0; mt < 2; ++mt)
            #pragma unroll
            for (int nt = 0; nt < 8; ++nt)
                #pragma unroll
                for (int e = 0; e < 4; ++e) acc[mt][nt][e] = 0.0f;

        float4 aReg[2];
        int4   bhReg[2], blReg[2];

        auto load_regs = [&](int kc) {
            const int k0 = kc * 32;
            #pragma unroll
            for (int it = 0; it < 2; ++it) {
                int f = tid + it * 512;
                int r = f >> 3, c4 = (f & 7) * 4;
                aReg[it] = *(const float4*)(inp + (size_t)(rowTile + r) * HH + k0 + c4);
            }
            #pragma unroll
            for (int it = 0; it < 2; ++it) {
                int gI = tid + it * 512;
                int r = gI >> 2, c8 = (gI & 3) * 8;
                bhReg[it] = *(const int4*)(Bh + (size_t)r * HH + k0 + c8);
                blReg[it] = *(const int4*)(Bl + (size_t)r * HH + k0 + c8);
            }
        };

        load_regs(0);

        for (int kc = 0; kc < 8; ++kc) {
            const int s = kc & 1;
            const uint32_t aS = sbA + (uint32_t)s * ABUF;
            const uint32_t bS = sbB + (uint32_t)s * BBUF;

            // ---- convert + store prefetched regs into stage s ----
            #pragma unroll
            for (int it = 0; it < 2; ++it) {
                int f = tid + it * 512;
                int r = f >> 3, c4 = (f & 7) * 4;
                float xv[4] = {aReg[it].x, aReg[it].y, aReg[it].z, aReg[it].w};
                unsigned short h[4], q[4];
                #pragma unroll
                for (int e = 0; e < 4; ++e) {
                    __nv_bfloat16 bh = __float2bfloat16(xv[e]);
                    h[e] = __bfloat16_as_ushort(bh);
                    q[e] = __bfloat16_as_ushort(
                        __float2bfloat16(xv[e] - __bfloat162float(bh)));
                }
                uint2 hv = make_uint2(h[0] | ((uint32_t)h[1] << 16),
                                      h[2] | ((uint32_t)h[3] << 16));
                uint2 lv = make_uint2(q[0] | ((uint32_t)q[1] << 16),
                                      q[2] | ((uint32_t)q[3] << 16));
                *(uint2*)(smem + OFF_A + s * ABUF + ((size_t)r * PADK + c4) * 2) = hv;
                *(uint2*)(smem + OFF_A + s * ABUF + ((size_t)(128 + r) * PADK + c4) * 2) = lv;
            }
            #pragma unroll
            for (int it = 0; it < 2; ++it) {
                int gI = tid + it * 512;
                int r = gI >> 2, c8 = (gI & 3) * 8;
                *(int4*)(smem + OFF_B + s * BBUF + ((size_t)r * PADK + c8) * 2) = bhReg[it];
                *(int4*)(smem + OFF_B + s * BBUF + ((size_t)(256 + r) * PADK + c8) * 2) = blReg[it];
            }
            __syncthreads();

            if (kc < 7) load_regs(kc + 1);    // overlap next global loads with compute

            #pragma unroll
            for (int ks = 0; ks < 2; ++ks) {
                const int kk = ks * 16;
                uint32_t ah[2][4], al[2][4];
                #pragma unroll
                for (int mt = 0; mt < 2; ++mt) {
                    int row = warpRow * 32 + mt * 16 + (lane & 15);
                    int kcol = kk + (lane >> 4) * 8;
                    uint32_t ad = aS + (uint32_t)(row * PADK + kcol) * 2;
                    LDSM_X4(ah[mt][0], ah[mt][1], ah[mt][2], ah[mt][3], ad);
                    LDSM_X4(al[mt][0], al[mt][1], al[mt][2], al[mt][3],
                            ad + 128 * PADK * 2);
                }
                #pragma unroll
                for (int p = 0; p < 4; ++p) {
                    int row = warpCol * 64 + p * 16 + (lane & 7) + ((lane >> 4) << 3);
                    int kcol = kk + (((lane >> 3) & 1) << 3);
                    uint32_t bd = bS + (uint32_t)(row * PADK + kcol) * 2;
                    uint32_t bh[4], bl[4];
                    LDSM_X4(bh[0], bh[1], bh[2], bh[3], bd);
                    LDSM_X4(bl[0], bl[1], bl[2], bl[3], bd + 256 * PADK * 2);
                    #pragma unroll
                    for (int mt = 0; mt < 2; ++mt) {
                        MMA_BF16(acc[mt][2 * p],     ah[mt], bh[0], bh[1]);
                        MMA_BF16(acc[mt][2 * p],     al[mt], bh[0], bh[1]);
                        MMA_BF16(acc[mt][2 * p],     ah[mt], bl[0], bl[1]);
                        MMA_BF16(acc[mt][2 * p + 1], ah[mt], bh[2], bh[3]);
                        MMA_BF16(acc[mt][2 * p + 1], al[mt], bh[2], bh[3]);
                        MMA_BF16(acc[mt][2 * p + 1], ah[mt], bl[2], bl[3]);
                    }
                }
            }
        }

        // ---- epilogue: fp16 Wh store + fused s1/s2 dots (unchanged) ----
        __syncthreads();
        const int g = lane >> 2, qc = (lane & 3) * 2;
        #pragma unroll
        for (int mt = 0; mt < 2; ++mt) {
            int lr0 = warpRow * 32 + mt * 16 + g;
            int lr1 = lr0 + 8;
            int gr0 = rowTile + lr0, gr1 = rowTile + lr1;   // global (addressing)
            int nr0 = n0 + lr0, nr1 = n0 + lr1;             // within-batch (masking)
            bool dw0 = !mixed || (((nr0 >= l0) && (nr0 < l1)) == useWi);
            bool dw1 = !mixed || (((nr1 >= l0) && (nr1 < l1)) == useWi);
            float s1r0 = 0, s2r0 = 0, s1r1 = 0, s2r1 = 0;
            #pragma unroll
            for (int nt = 0; nt < 8; ++nt) {
                int col = warpCol * 64 + nt * 8 + qc;
                float a0 = sAv[col], a1 = sAv[col + 1];
                float b0 = sAv[256 + col], b1 = sAv[256 + col + 1];
                float c0 = acc[mt][nt][0], c1 = acc[mt][nt][1];
                float c2 = acc[mt][nt][2], c3 = acc[mt][nt][3];
                s1r0 = fmaf(c0, a0, fmaf(c1, a1, s1r0));
                s2r0 = fmaf(c0, b0, fmaf(c1, b1, s2r0));
                s1r1 = fmaf(c2, a0, fmaf(c3, a1, s1r1));
                s2r1 = fmaf(c2, b0, fmaf(c3, b1, s2r1));
                if (dw0)
                    *(__half2*)(g_WhH + (size_t)gr0 * HH + col) = __floats2half2_rn(c0, c1);
                if (dw1)
                    *(__half2*)(g_WhH + (size_t)gr1 * HH + col) = __floats2half2_rn(c2, c3);
            }
            #pragma unroll
            for (int d = 1; d <= 2; d <<= 1) {
                s1r0 += __shfl_xor_sync(0xffffffffu, s1r0, d);
                s2r0 += __shfl_xor_sync(0xffffffffu, s2r0, d);
                s1r1 += __shfl_xor_sync(0xffffffffu, s1r1, d);
                s2r1 += __shfl_xor_sync(0xffffffffu, s2r1, d);
            }
            if ((lane & 3) == 0) {
                sRed[(warpCol * 128 + lr0) * 2 + 0] = s1r0;
                sRed[(warpCol * 128 + lr0) * 2 + 1] = s2r0;
                sRed[(warpCol * 128 + lr1) * 2 + 0] = s1r1;
                sRed[(warpCol * 128 + lr1) * 2 + 1] = s2r1;
            }
        }
        __syncthreads();
        if (tid < 128) {
            int grow = rowTile + tid;
            int nrow = n0 + tid;
            bool dw = !mixed || (((nrow >= l0) && (nrow < l1)) == useWi);
            if (dw) {
                float v1 = 0, v2 = 0;
                #pragma unroll
                for (int wc = 0; wc < 4; ++wc) {
                    v1 += sRed[(wc * 128 + tid) * 2 + 0];
                    v2 += sRed[(wc * 128 + tid) * 2 + 1];
                }
                g_s1[grow] = v1;
                g_s2[grow] = v2;
            }
        }
        __syncthreads();
    }
}

// ---------------------------------------------------------------------------
// Kernel 2: masked softmax -> dense fp16 normalized att row.
// ---------------------------------------------------------------------------
__global__ __launch_bounds__(128) void score_kernel(
    const float* __restrict__ A, __half* __restrict__ att)
{
    __shared__ float s_red[8];

    const int bi = blockIdx.x;
    const int b = bi >> 10, i = bi & 1023;
    const int tid = threadIdx.x, lane = tid & 31, w = tid >> 5;
    const float* Arow = A + (size_t)bi * NN;
    const float* s2b = g_s2 + (size_t)b * NN;
    const float s1i = g_s1[bi];

    float av[8];
    {
        float4 v0 = *(const float4*)(Arow + tid * 8);
        float4 v1 = *(const float4*)(Arow + tid * 8 + 4);
        av[0] = v0.x; av[1] = v0.y; av[2] = v0.z; av[3] = v0.w;
        av[4] = v1.x; av[5] = v1.y; av[6] = v1.z; av[7] = v1.w;
    }
    unsigned pbits = 0;
    float xv[8];
    float lmax = -INFINITY;
    #pragma unroll
    for (int q = 0; q < 8; ++q) {
        int j = tid * 8 + q;
        float aval = av[q] + ((j == i) ? 1.0f : 0.0f);   // A + I (diag may be 2)
        if (aval > 0.0f) {
            float x = (s1i + s2b[j]) * aval;
            x = (x > 0.0f) ? x : 0.2f * x;               // leaky relu
            xv[q] = x;
            pbits |= (1u << q);
            lmax = fmaxf(lmax, x);
        }
    }
    float wm = lmax;
    #pragma unroll
    for (int d = 16; d > 0; d >>= 1) wm = fmaxf(wm, __shfl_xor_sync(0xffffffffu, wm, d));
    if (lane == 0) s_red[w] = wm;
    __syncthreads();
    const float m = fmaxf(fmaxf(s_red[0], s_red[1]), fmaxf(s_red[2], s_red[3]));

    float wv[8];
    float lz = 0.0f;
    #pragma unroll
    for (int q = 0; q < 8; ++q) {
        float e = (pbits & (1u << q)) ? __expf(xv[q] - m) : 0.0f;
        wv[q] = e;
        lz += e;
    }
    #pragma unroll
    for (int d = 16; d > 0; d >>= 1) lz += __shfl_xor_sync(0xffffffffu, lz, d);
    if (lane == 0) s_red[4 + w] = lz;
    __syncthreads();
    const float Zi = 1.0f / (s_red[4] + s_red[5] + s_red[6] + s_red[7]);

    __half2 hv[4];
    #pragma unroll
    for (int q = 0; q < 4; ++q)
        hv[q] = __floats2half2_rn(wv[2 * q] * Zi, wv[2 * q + 1] * Zi);
    *(int4*)(att + (size_t)bi * NN + tid * 8) = *(const int4*)hv;
}

// ---------------------------------------------------------------------------
// Kernel 3 v3: out = elu(att @ Wh). 64x256 tile per CTA, 256 threads,
// 2 CTAs/SM (__launch_bounds__(256,2)). 2-stage cp.async pipeline, K-chunk 64.
// Per-warp fragment code identical to the validated v2.
// ---------------------------------------------------------------------------
#define BPADK 72
#define B_A_STAGE (64 * BPADK * 2)           // 9216
#define B_B_STAGE (64 * 264 * 2)             // 33792
#define BOFF_B (2 * B_A_STAGE)               // 18432
#define BSMEM_TOT (BOFF_B + 2 * B_B_STAGE)   // 86016

__global__ __launch_bounds__(256, 2) void bmm_kernel(
    const __half* __restrict__ att, const __half* __restrict__ Wh,
    float* __restrict__ out)
{
    extern __shared__ char bsm[];
    const uint32_t aBase = smem_u32(bsm);
    const uint32_t bBase = aBase + BOFF_B;

    const int tid = threadIdx.x, lane = tid & 31, wid = tid >> 5;
    const int warpRow = wid >> 2, warpCol = wid & 3;      // 2 x 4 warps
    const int b  = blockIdx.x >> 4;
    const int rt = (blockIdx.x & 15) * 64;
    const __half* attB = att + ((size_t)b * NN + rt) * NN;
    const __half* WhB  = Wh + (size_t)b * NN * HH;

    float acc[2][8][4];
    #pragma unroll
    for (int mt = 0; mt < 2; ++mt)
        #pragma unroll
        for (int nt = 0; nt < 8; ++nt)
            #pragma unroll
            for (int e = 0; e < 4; ++e) acc[mt][nt][e] = 0.0f;

    auto load_stage = [&](int kc, int s) {
        const int k0 = kc * 64;
        uint32_t aS = aBase + (uint32_t)s * B_A_STAGE;
        uint32_t bS = bBase + (uint32_t)s * B_B_STAGE;
        #pragma unroll
        for (int it = 0; it < 2; ++it) {
            int f = tid + it * 256;                 // 0..511 : 64 rows x 8 segs
            int r = f >> 3, c = (f & 7) * 8;
            CP16(aS + (uint32_t)(r * BPADK + c) * 2,
                 attB + (size_t)r * NN + k0 + c);
        }
        #pragma unroll
        for (int it = 0; it < 8; ++it) {
            int f = tid + it * 256;                 // 0..2047 : 64 rows x 32 segs
            int r = f >> 5, c = (f & 31) * 8;
            CP16(bS + (uint32_t)(r * 264 + c) * 2,
                 WhB + (size_t)(k0 + r) * HH + c);
        }
        CP_COMMIT();
    };

    load_stage(0, 0);

    for (int kc = 0; kc < 16; ++kc) {
        const int s = kc & 1;
        if (kc + 1 < 16) {
            load_stage(kc + 1, s ^ 1);
            asm volatile("cp.async.wait_group 1;" ::: "memory");
        } else {
            asm volatile("cp.async.wait_group 0;" ::: "memory");
        }
        __syncthreads();

        const uint32_t aS = aBase + (uint32_t)s * B_A_STAGE;
        const uint32_t bS = bBase + (uint32_t)s * B_B_STAGE;
        #pragma unroll
        for (int ks = 0; ks < 4; ++ks) {
            const int kk = ks * 16;
            uint32_t a[2][4];
            #pragma unroll
            for (int mt = 0; mt < 2; ++mt) {
                int row = warpRow * 32 + mt * 16 + (lane & 15);
                int kcol = kk + (lane >> 4) * 8;
                LDSM_X4(a[mt][0], a[mt][1], a[mt][2], a[mt][3],
                        aS + (uint32_t)(row * BPADK + kcol) * 2);
            }
            #pragma unroll
            for (int p = 0; p < 4; ++p) {
                int n = warpCol * 64 + p * 16;
                int krow = kk + (lane & 15);
                int col = n + ((lane >> 4) << 3);
                uint32_t bfr[4];
                LDSM_X4_T(bfr[0], bfr[1], bfr[2], bfr[3],
                          bS + (uint32_t)(krow * 264 + col) * 2);
                #pragma unroll
                for (int mt = 0; mt < 2; ++mt) {
                    MMA_F16(acc[mt][2 * p],     a[mt], bfr[0], bfr[1]);
                    MMA_F16(acc[mt][2 * p + 1], a[mt], bfr[2], bfr[3]);
                }
            }
        }
        __syncthreads();   // stage s free for reuse at kc+2
    }

    // ---- epilogue: elu + fp32 store ----
    const int g = lane >> 2, qc = (lane & 3) * 2;
    #pragma unroll
    for (int mt = 0; mt < 2; ++mt) {
        int lr0 = warpRow * 32 + mt * 16 + g;
        int lr1 = lr0 + 8;
        size_t o0 = ((size_t)b * NN + rt + lr0) * HH;
        size_t o1 = ((size_t)b * NN + rt + lr1) * HH;
        #pragma unroll
        for (int nt = 0; nt < 8; ++nt) {
            int col = warpCol * 64 + nt * 8 + qc;
            float c0 = acc[mt][nt][0], c1 = acc[mt][nt][1];
            float c2 = acc[mt][nt][2], c3 = acc[mt][nt][3];
            float2 r0, r1;
            r0.x = (c0 > 0.0f) ? c0 : expm1f(c0);
            r0.y = (c1 > 0.0f) ? c1 : expm1f(c1);
            r1.x = (c2 > 0.0f) ? c2 : expm1f(c2);
            r1.y = (c3 > 0.0f) ? c3 : expm1f(c3);
            *(float2*)(out + o0 + col) = r0;
            *(float2*)(out + o1 + col) = r1;
        }
    }
}

// ---------------------------------------------------------------------------
extern "C" void kernel_launch(void* const* d_in, const int* in_sizes, int n_in,
                              void* d_out, int out_size)
{
    const float* inp = (const float*)d_in[0];   // [B,N,H]
    const float* A   = (const float*)d_in[1];   // [B,N,N]
    const int*   l   = (const int*)  d_in[2];   // [B,2]
    const float* Wi  = (const float*)d_in[3];   // [H,H]
    const float* Wc  = (const float*)d_in[4];   // [H,H]
    const float* a   = (const float*)d_in[5];   // [2H,1]
    float* out = (float*)d_out;

    __half *WhH, *att;
    cudaGetSymbolAddress((void**)&WhH, g_WhH);
    cudaGetSymbolAddress((void**)&att, g_att);

    cudaFuncSetAttribute(gemm_kernel, cudaFuncAttributeMaxDynamicSharedMemorySize, SMEM_TOT);
    cudaFuncSetAttribute(bmm_kernel, cudaFuncAttributeMaxDynamicSharedMemorySize, BSMEM_TOT);

    wsplit_kernel<<<2 * HH * HH / 256, 256>>>(Wi, Wc);
    gemm_kernel<<<BB * NN / 128, 512, SMEM_TOT>>>(inp, l, a);
    score_kernel<<<BB * NN, 128>>>(A, att);
    bmm_kernel<<<BB * NN / 64, 256, BSMEM_TOT>>>(att, WhH, out);
}